// round 10
// baseline (speedup 1.0000x reference)
#include <cuda_runtime.h>
#include <cuda_bf16.h>
#include <cstdint>

#define NQ    10
#define DIM   1024
#define NL    4
#define BATCH 4096
#define SEQ   512
#define PRED  96

// ---------------- device scratch (allocation-free) ----------------
__device__ float         g_h[BATCH * DIM];       // 16 MB intermediate h
__device__ __nv_bfloat16 g_xhi[BATCH * SEQ];
__device__ __nv_bfloat16 g_xlo[BATCH * SEQ];
__device__ __nv_bfloat16 g_whi[DIM * SEQ];
__device__ __nv_bfloat16 g_wlo[DIM * SEQ];
__device__ float2        g_gates[NL * NQ * 4];
__device__ int           g_perm[NL * DIM];

// ---------------- kernel 0: bf16 hi/lo split + gate/perm precompute ----------------
__global__ void split_kernel(const float* __restrict__ x, const float* __restrict__ w,
                             const float* __restrict__ qw) {
    int i = blockIdx.x * blockDim.x + threadIdx.x;
    if (i < BATCH * SEQ) {
        float v = x[i];
        __nv_bfloat16 h = __float2bfloat16(v);
        g_xhi[i] = h;
        g_xlo[i] = __float2bfloat16(v - __bfloat162float(h));
    }
    if (i < DIM * SEQ) {
        float v = w[i];
        __nv_bfloat16 h = __float2bfloat16(v);
        g_whi[i] = h;
        g_wlo[i] = __float2bfloat16(v - __bfloat162float(h));
    }
    if (blockIdx.x == 0) {
        int t = threadIdx.x;
        if (t < NL * NQ) {
            float phi   = qw[3 * t + 0];
            float theta = qw[3 * t + 1];
            float omega = qw[3 * t + 2];
            float s, c;
            sincosf(0.5f * theta, &s, &c);
            float a = 0.5f * (phi + omega);
            float b = 0.5f * (phi - omega);
            float sa, ca, sb, cb;
            sincosf(a, &sa, &ca);
            sincosf(b, &sb, &cb);
            g_gates[4 * t + 0] = make_float2( c * ca, -c * sa);
            g_gates[4 * t + 1] = make_float2(-s * cb, -s * sb);
            g_gates[4 * t + 2] = make_float2( s * cb, -s * sb);
            g_gates[4 * t + 3] = make_float2( c * ca,  c * sa);
        }
        for (int e = t; e < DIM; e += blockDim.x) {
            for (int l = 0; l < NL; l++) {
                int r = l % (NQ - 1) + 1;
                int p = e;
                for (int c = NQ - 1; c >= 0; c--) {
                    int bit = (p >> (NQ - 1 - c)) & 1;
                    int tgt = (c + r) % NQ;
                    p ^= bit << (NQ - 1 - tgt);
                }
                g_perm[l * DIM + e] = p;
            }
        }
    }
}

// ---------------- kernel 2: bf16 tensor-core GEMM (3-product, 3-stage ring) ----------------
#define GBM 128
#define GBN 128
#define GBK 16
#define SROW 24                 // bf16 per smem row (16 + 8 pad) = 48 bytes
#define MATB (GBM * SROW * 2)   // bytes per matrix tile = 6144
#define STAGEB (4 * MATB)       // bytes per stage = 24576
#define NSTAGE 3

#define MMA_BF16(C, A, B)                                                       \
    asm volatile("mma.sync.aligned.m16n8k16.row.col.f32.bf16.bf16.f32 "         \
                 "{%0,%1,%2,%3}, {%4,%5,%6,%7}, {%8,%9}, {%0,%1,%2,%3};"        \
                 : "+f"((C)[0]), "+f"((C)[1]), "+f"((C)[2]), "+f"((C)[3])       \
                 : "r"((A)[0]), "r"((A)[1]), "r"((A)[2]), "r"((A)[3]),          \
                   "r"((B)[0]), "r"((B)[1]))

#define LDM4(R, addr)                                                           \
    asm volatile("ldmatrix.sync.aligned.m8n8.x4.shared.b16 {%0,%1,%2,%3},[%4];" \
                 : "=r"((R)[0]), "=r"((R)[1]), "=r"((R)[2]), "=r"((R)[3])       \
                 : "r"(addr))

#define CPASYNC16(dst, src)                                                     \
    asm volatile("cp.async.cg.shared.global [%0], [%1], 16;" ::                 \
                 "r"(dst), "l"(src))

__global__ __launch_bounds__(256) void gemm_tc(const float* __restrict__ bias) {
    extern __shared__ __nv_bfloat16 smem[];       // NSTAGE * STAGEB = 73728 bytes
    const int tid  = threadIdx.x;
    const int lane = tid & 31, wid = tid >> 5;
    const int wm = wid >> 2, wn = wid & 3;        // 2(m) x 4(n) warps; warp tile 64x32
    const int bm = blockIdx.y * GBM, bn = blockIdx.x * GBN;
    const int g = lane >> 2, tg = lane & 3;

    const uint32_t sbase = (uint32_t)__cvta_generic_to_shared(smem);

    float c[4][4][4];
#pragma unroll
    for (int mi = 0; mi < 4; mi++)
#pragma unroll
        for (int ni = 0; ni < 4; ni++)
#pragma unroll
            for (int k = 0; k < 4; k++) c[mi][ni][k] = 0.f;

    const int lr = tid >> 1, lc = tid & 1;
    const size_t offA = (size_t)(bm + lr) * SEQ + lc * 8;
    const size_t offB = (size_t)(bn + lr) * SEQ + lc * 8;
    const uint32_t ldst = (uint32_t)(lr * SROW + lc * 8) * 2;

    auto load_stage = [&](int st, int k0) {
        uint32_t d = sbase + st * STAGEB + ldst;
        CPASYNC16(d + 0 * MATB, g_xhi + offA + k0);
        CPASYNC16(d + 1 * MATB, g_xlo + offA + k0);
        CPASYNC16(d + 2 * MATB, g_whi + offB + k0);
        CPASYNC16(d + 3 * MATB, g_wlo + offB + k0);
        asm volatile("cp.async.commit_group;");
    };

    const int rA   = (lane & 7) + ((lane >> 3) & 1) * 8;
    const int colo = (lane >> 4) * 16;

    load_stage(0, 0);
    load_stage(1, GBK);

    const int NIT = SEQ / GBK;                    // 32
    int slot = 0;                                  // ring slot of current stage
    for (int it = 0; it < NIT; it++) {
        asm volatile("cp.async.wait_group 1;");
        __syncthreads();
        // issue load for it+2 into slot (it+2)%3 == (it-1)%3 (consumed last iter; safe after sync)
        int nxt = it + 2;
        if (nxt < NIT) {
            int ns = slot + 2;
            if (ns >= NSTAGE) ns -= NSTAGE;
            load_stage(ns, nxt * GBK);
        } else {
            asm volatile("cp.async.commit_group;");
        }

        const uint32_t st = sbase + slot * STAGEB;
        unsigned ah[4][4], al[4][4], bh[4][2], bl[4][2];
#pragma unroll
        for (int mi = 0; mi < 4; mi++) {
            uint32_t ad = st + (uint32_t)((wm * 64 + mi * 16 + rA) * SROW) * 2 + colo;
            LDM4(ah[mi], ad);
            LDM4(al[mi], ad + MATB);
        }
#pragma unroll
        for (int nj = 0; nj < 2; nj++) {
            uint32_t bd = st + 2 * MATB + (uint32_t)((wn * 32 + nj * 16 + rA) * SROW) * 2 + colo;
            unsigned r[4];
            LDM4(r, bd);
            bh[2 * nj][0] = r[0]; bh[2 * nj + 1][0] = r[1];
            bh[2 * nj][1] = r[2]; bh[2 * nj + 1][1] = r[3];
            LDM4(r, bd + MATB);
            bl[2 * nj][0] = r[0]; bl[2 * nj + 1][0] = r[1];
            bl[2 * nj][1] = r[2]; bl[2 * nj + 1][1] = r[3];
        }
#pragma unroll
        for (int mi = 0; mi < 4; mi++)
#pragma unroll
            for (int ni = 0; ni < 4; ni++) {
                MMA_BF16(c[mi][ni], ah[mi], bh[ni]);
                MMA_BF16(c[mi][ni], ah[mi], bl[ni]);
                MMA_BF16(c[mi][ni], al[mi], bh[ni]);
            }
        if (++slot == NSTAGE) slot = 0;
    }

#pragma unroll
    for (int mi = 0; mi < 4; mi++) {
        int r0 = bm + wm * 64 + mi * 16 + g;
#pragma unroll
        for (int ni = 0; ni < 4; ni++) {
            int cc = bn + wn * 32 + ni * 8 + 2 * tg;
            float b0 = bias[cc] + 1e-6f;
            float b1 = bias[cc + 1] + 1e-6f;
            g_h[(size_t)r0 * DIM + cc]           = c[mi][ni][0] + b0;
            g_h[(size_t)r0 * DIM + cc + 1]       = c[mi][ni][1] + b1;
            g_h[(size_t)(r0 + 8) * DIM + cc]     = c[mi][ni][2] + b0;
            g_h[(size_t)(r0 + 8) * DIM + cc + 1] = c[mi][ni][3] + b1;
        }
    }
}

// ---------------- kernel 3: circuit, 8 amps/thread, 128 threads (R7 proven) ----------------
__device__ __forceinline__ void rot1(float2 va, float2 vb, float& r, float& i,
                                     float pr, float pi) {
    float nr = va.x * r - va.y * i + vb.x * pr - vb.y * pi;
    float ni = va.x * i + va.y * r + vb.x * pi + vb.y * pr;
    r = nr; i = ni;
}

__global__ __launch_bounds__(128, 8) void circuit_kernel(const float* __restrict__ Wout,
                                                         const float* __restrict__ bout,
                                                         float* __restrict__ out) {
    __shared__ float4 xchg[640];                 // exchange buf (stride-5 float4) / perm stage
    __shared__ float2 sg[NL * NQ * 4];
    __shared__ float  red[4][9];
    __shared__ float  sevn[NQ];
    float2* stage = (float2*)xchg;               // 1024 float2 = 8KB, fits in xchg

    const int t    = threadIdx.x;
    const int lane = t & 31;
    const int b    = blockIdx.x;

    // amp j = 8*t + a : bits 0-2 local, 3-7 lane, 8-9 warp
    const float* hrow = g_h + (size_t)b * DIM + 8 * t;
    float4 hA = *(const float4*)hrow;
    float4 hB = *(const float4*)(hrow + 4);
    float ar[8] = {hA.x, hA.y, hA.z, hA.w, hB.x, hB.y, hB.z, hB.w};
    float ai[8] = {0.f, 0.f, 0.f, 0.f, 0.f, 0.f, 0.f, 0.f};

    for (int i = t; i < NL * NQ * 4; i += 128) sg[i] = g_gates[i];
    __syncthreads();

    for (int l = 0; l < NL; l++) {
        const float2* gl = sg + l * NQ * 4;

        // w=0,1 -> m=9,8 : smem exchange with thread t^64 / t^32
#pragma unroll
        for (int w = 0; w < 2; w++) {
            const float2 u00 = gl[4 * w + 0], u01 = gl[4 * w + 1];
            const float2 u10 = gl[4 * w + 2], u11 = gl[4 * w + 3];
            const int pmask = w ? 32 : 64;
#pragma unroll
            for (int k = 0; k < 4; k++)
                xchg[t * 5 + k] = make_float4(ar[2 * k], ai[2 * k], ar[2 * k + 1], ai[2 * k + 1]);
            __syncthreads();
            const int pth = t ^ pmask;
            float4 o0 = xchg[pth * 5 + 0];
            float4 o1 = xchg[pth * 5 + 1];
            float4 o2 = xchg[pth * 5 + 2];
            float4 o3 = xchg[pth * 5 + 3];
            __syncthreads();
            const bool hib = (t & pmask) != 0;
            const float2 va = hib ? u11 : u00;
            const float2 vb = hib ? u10 : u01;
            rot1(va, vb, ar[0], ai[0], o0.x, o0.y);
            rot1(va, vb, ar[1], ai[1], o0.z, o0.w);
            rot1(va, vb, ar[2], ai[2], o1.x, o1.y);
            rot1(va, vb, ar[3], ai[3], o1.z, o1.w);
            rot1(va, vb, ar[4], ai[4], o2.x, o2.y);
            rot1(va, vb, ar[5], ai[5], o2.z, o2.w);
            rot1(va, vb, ar[6], ai[6], o3.x, o3.y);
            rot1(va, vb, ar[7], ai[7], o3.z, o3.w);
        }

        // w=2..6 -> m=7..3 : shfl over lane bit (6-w)
#pragma unroll
        for (int w = 2; w < 7; w++) {
            const float2 u00 = gl[4 * w + 0], u01 = gl[4 * w + 1];
            const float2 u10 = gl[4 * w + 2], u11 = gl[4 * w + 3];
            const int msk = 1 << (6 - w);
            const bool hib = (lane & msk) != 0;
            const float2 va = hib ? u11 : u00;
            const float2 vb = hib ? u10 : u01;
#pragma unroll
            for (int a = 0; a < 8; a++) {
                float pr = __shfl_xor_sync(0xffffffffu, ar[a], msk);
                float pi = __shfl_xor_sync(0xffffffffu, ai[a], msk);
                rot1(va, vb, ar[a], ai[a], pr, pi);
            }
        }

        // w=7,8,9 -> m=2,1,0 : local pairs
#pragma unroll
        for (int w = 7; w < 10; w++) {
            const float2 u00 = gl[4 * w + 0], u01 = gl[4 * w + 1];
            const float2 u10 = gl[4 * w + 2], u11 = gl[4 * w + 3];
            const int dm = 1 << (9 - w);
#pragma unroll
            for (int a = 0; a < 8; a++) {
                if (!(a & dm)) {
                    float lr = ar[a], li = ai[a];
                    float hr = ar[a + dm], hi2 = ai[a + dm];
                    ar[a]      = u00.x * lr - u00.y * li + u01.x * hr - u01.y * hi2;
                    ai[a]      = u00.x * li + u00.y * lr + u01.x * hi2 + u01.y * hr;
                    ar[a + dm] = u10.x * lr - u10.y * li + u11.x * hr - u11.y * hi2;
                    ai[a + dm] = u10.x * li + u10.y * lr + u11.x * hi2 + u11.y * hr;
                }
            }
        }

        // layer permutation: psi_new[j] = psi[perm[j]]; stage layout [a-plane][t]
#pragma unroll
        for (int a = 0; a < 8; a++) stage[a * 128 + t] = make_float2(ar[a], ai[a]);
        __syncthreads();
        const int* pm = g_perm + l * DIM + 8 * t;
        int4 pa = *(const int4*)pm;
        int4 pb = *(const int4*)(pm + 4);
        int pp[8] = {pa.x, pa.y, pa.z, pa.w, pb.x, pb.y, pb.z, pb.w};
        float2 nv[8];
#pragma unroll
        for (int a = 0; a < 8; a++) {
            int p = pp[a];
            nv[a] = stage[(p & 7) * 128 + (p >> 3)];
        }
        __syncthreads();
#pragma unroll
        for (int a = 0; a < 8; a++) { ar[a] = nv[a].x; ai[a] = nv[a].y; }
    }

    // expvals (unnormalized; divide by total prob at the end)
    float p[8];
#pragma unroll
    for (int a = 0; a < 8; a++) p[a] = ar[a] * ar[a] + ai[a] * ai[a];
    float ps = ((p[0] + p[1]) + (p[2] + p[3])) + ((p[4] + p[5]) + (p[6] + p[7]));

    float v[9];
    v[0] = ps;
#pragma unroll
    for (int i = 0; i < 5; i++)                              // q = 2+i, lane bit 4-i
        v[1 + i] = ((lane >> (4 - i)) & 1) ? -ps : ps;
    v[6] = ((p[0] + p[1]) + (p[2] + p[3])) - ((p[4] + p[5]) + (p[6] + p[7]));  // q7
    v[7] = ((p[0] + p[1]) + (p[4] + p[5])) - ((p[2] + p[3]) + (p[6] + p[7]));  // q8
    v[8] = ((p[0] + p[2]) + (p[4] + p[6])) - ((p[1] + p[3]) + (p[5] + p[7]));  // q9

#pragma unroll
    for (int j = 0; j < 9; j++) {
#pragma unroll
        for (int o = 16; o; o >>= 1) v[j] += __shfl_xor_sync(0xffffffffu, v[j], o);
    }
    if (lane == 0) {
        int wi = t >> 5;
#pragma unroll
        for (int j = 0; j < 9; j++) red[wi][j] = v[j];
    }
    __syncthreads();

    if (t < NQ) {
        const int q = t;
        float pst = ((red[0][0] + red[1][0]) + (red[2][0] + red[3][0]));
        float e;
        if (q >= 2) {
            e = ((red[0][q - 1] + red[1][q - 1]) + (red[2][q - 1] + red[3][q - 1]));
        } else if (q == 0) {   // j bit9 = warp bit1
            e = (red[0][0] + red[1][0]) - (red[2][0] + red[3][0]);
        } else {               // j bit8 = warp bit0
            e = (red[0][0] - red[1][0]) + (red[2][0] - red[3][0]);
        }
        sevn[q] = e / pst;
    }
    __syncthreads();

    if (t < PRED) {
        float o = bout[t];
#pragma unroll
        for (int q = 0; q < NQ; q++) o += sevn[q] * Wout[t * NQ + q];
        out[(size_t)b * PRED + t] = o;
    }
}

// ---------------- launch ----------------
extern "C" void kernel_launch(void* const* d_in, const int* in_sizes, int n_in,
                              void* d_out, int out_size) {
    const float* x     = (const float*)d_in[0];
    const float* W_in  = (const float*)d_in[1];
    const float* b_in  = (const float*)d_in[2];
    const float* qw    = (const float*)d_in[3];
    const float* W_out = (const float*)d_in[4];
    const float* b_out = (const float*)d_in[5];
    float* out = (float*)d_out;

    cudaFuncSetAttribute(gemm_tc, cudaFuncAttributeMaxDynamicSharedMemorySize,
                         NSTAGE * STAGEB);

    split_kernel<<<(BATCH * SEQ + 255) / 256, 256>>>(x, W_in, qw);
    dim3 grid(DIM / GBN, BATCH / GBM);
    gemm_tc<<<grid, 256, NSTAGE * STAGEB>>>(b_in);
    circuit_kernel<<<BATCH, 128>>>(W_out, b_out, out);
}

// round 12
// speedup vs baseline: 1.5593x; 1.5593x over previous
#include <cuda_runtime.h>
#include <cuda_bf16.h>
#include <cstdint>

#define NQ    10
#define DIM   1024
#define NL    4
#define BATCH 4096
#define SEQ   512
#define PRED  96

// ---------------- device scratch (allocation-free) ----------------
__device__ float         g_h[BATCH * DIM];       // 16 MB intermediate h
__device__ __nv_bfloat16 g_xhi[BATCH * SEQ];
__device__ __nv_bfloat16 g_xlo[BATCH * SEQ];
__device__ __nv_bfloat16 g_whi[DIM * SEQ];
__device__ __nv_bfloat16 g_wlo[DIM * SEQ];
__device__ float2        g_gates[NL * NQ * 4];
__device__ int           g_perm[NL * DIM];

// ---------------- kernel 0: vectorized bf16 hi/lo split + gate/perm precompute ----------------
__device__ __forceinline__ void split4(float4 v, __nv_bfloat162* hi, __nv_bfloat162* lo) {
    __nv_bfloat16 hx = __float2bfloat16(v.x), hy = __float2bfloat16(v.y);
    __nv_bfloat16 hz = __float2bfloat16(v.z), hw = __float2bfloat16(v.w);
    hi[0] = __nv_bfloat162(hx, hy);
    hi[1] = __nv_bfloat162(hz, hw);
    lo[0] = __nv_bfloat162(__float2bfloat16(v.x - __bfloat162float(hx)),
                           __float2bfloat16(v.y - __bfloat162float(hy)));
    lo[1] = __nv_bfloat162(__float2bfloat16(v.z - __bfloat162float(hz)),
                           __float2bfloat16(v.w - __bfloat162float(hw)));
}

__global__ void split_kernel(const float* __restrict__ x, const float* __restrict__ w,
                             const float* __restrict__ qw) {
    int i4 = blockIdx.x * blockDim.x + threadIdx.x;     // one float4 per thread
    if (i4 < (BATCH * SEQ) / 4) {
        float4 v = *(const float4*)(x + 4 * i4);
        __nv_bfloat162 hi[2], lo[2];
        split4(v, hi, lo);
        *(__nv_bfloat162*)(g_xhi + 4 * i4)     = hi[0];
        *(__nv_bfloat162*)(g_xhi + 4 * i4 + 2) = hi[1];
        *(__nv_bfloat162*)(g_xlo + 4 * i4)     = lo[0];
        *(__nv_bfloat162*)(g_xlo + 4 * i4 + 2) = lo[1];
    }
    if (i4 < (DIM * SEQ) / 4) {
        float4 v = *(const float4*)(w + 4 * i4);
        __nv_bfloat162 hi[2], lo[2];
        split4(v, hi, lo);
        *(__nv_bfloat162*)(g_whi + 4 * i4)     = hi[0];
        *(__nv_bfloat162*)(g_whi + 4 * i4 + 2) = hi[1];
        *(__nv_bfloat162*)(g_wlo + 4 * i4)     = lo[0];
        *(__nv_bfloat162*)(g_wlo + 4 * i4 + 2) = lo[1];
    }
    if (blockIdx.x == 0) {
        int t = threadIdx.x;
        if (t < NL * NQ) {
            float phi   = qw[3 * t + 0];
            float theta = qw[3 * t + 1];
            float omega = qw[3 * t + 2];
            float s, c;
            sincosf(0.5f * theta, &s, &c);
            float a = 0.5f * (phi + omega);
            float b = 0.5f * (phi - omega);
            float sa, ca, sb, cb;
            sincosf(a, &sa, &ca);
            sincosf(b, &sb, &cb);
            g_gates[4 * t + 0] = make_float2( c * ca, -c * sa);
            g_gates[4 * t + 1] = make_float2(-s * cb, -s * sb);
            g_gates[4 * t + 2] = make_float2( s * cb, -s * sb);
            g_gates[4 * t + 3] = make_float2( c * ca,  c * sa);
        }
        for (int e = t; e < DIM; e += blockDim.x) {
            for (int l = 0; l < NL; l++) {
                int r = l % (NQ - 1) + 1;
                int p = e;
                for (int c = NQ - 1; c >= 0; c--) {
                    int bit = (p >> (NQ - 1 - c)) & 1;
                    int tgt = (c + r) % NQ;
                    p ^= bit << (NQ - 1 - tgt);
                }
                g_perm[l * DIM + e] = p;
            }
        }
    }
}

// ---------------- kernel 2: bf16 tensor-core GEMM (3-product, 2-stage, R7 proven) ----------------
#define GBM 128
#define GBN 128
#define GBK 16
#define SROW 24                 // bf16 per smem row (16 + 8 pad) = 48 bytes
#define MATB (GBM * SROW * 2)   // bytes per matrix tile = 6144
#define STAGEB (4 * MATB)       // bytes per stage = 24576

#define MMA_BF16(C, A, B)                                                       \
    asm volatile("mma.sync.aligned.m16n8k16.row.col.f32.bf16.bf16.f32 "         \
                 "{%0,%1,%2,%3}, {%4,%5,%6,%7}, {%8,%9}, {%0,%1,%2,%3};"        \
                 : "+f"((C)[0]), "+f"((C)[1]), "+f"((C)[2]), "+f"((C)[3])       \
                 : "r"((A)[0]), "r"((A)[1]), "r"((A)[2]), "r"((A)[3]),          \
                   "r"((B)[0]), "r"((B)[1]))

#define LDM4(R, addr)                                                           \
    asm volatile("ldmatrix.sync.aligned.m8n8.x4.shared.b16 {%0,%1,%2,%3},[%4];" \
                 : "=r"((R)[0]), "=r"((R)[1]), "=r"((R)[2]), "=r"((R)[3])       \
                 : "r"(addr))

#define CPASYNC16(dst, src)                                                     \
    asm volatile("cp.async.cg.shared.global [%0], [%1], 16;" ::                 \
                 "r"(dst), "l"(src))

__global__ __launch_bounds__(256) void gemm_tc(const float* __restrict__ bias) {
    __shared__ __nv_bfloat16 smem[2 * 4 * GBM * SROW];   // 49152 bytes
    const int tid  = threadIdx.x;
    const int lane = tid & 31, wid = tid >> 5;
    const int wm = wid >> 2, wn = wid & 3;               // 2(m) x 4(n) warps; warp tile 64x32
    const int bm = blockIdx.y * GBM, bn = blockIdx.x * GBN;
    const int g = lane >> 2, tg = lane & 3;

    const uint32_t sbase = (uint32_t)__cvta_generic_to_shared(smem);

    float c[4][4][4];
#pragma unroll
    for (int mi = 0; mi < 4; mi++)
#pragma unroll
        for (int ni = 0; ni < 4; ni++)
#pragma unroll
            for (int k = 0; k < 4; k++) c[mi][ni][k] = 0.f;

    const int lr = tid >> 1, lc = tid & 1;
    const size_t offA = (size_t)(bm + lr) * SEQ + lc * 8;
    const size_t offB = (size_t)(bn + lr) * SEQ + lc * 8;
    const uint32_t ldst = (uint32_t)(lr * SROW + lc * 8) * 2;

    auto load_stage = [&](int st, int k0) {
        uint32_t d = sbase + st * STAGEB + ldst;
        CPASYNC16(d + 0 * MATB, g_xhi + offA + k0);
        CPASYNC16(d + 1 * MATB, g_xlo + offA + k0);
        CPASYNC16(d + 2 * MATB, g_whi + offB + k0);
        CPASYNC16(d + 3 * MATB, g_wlo + offB + k0);
        asm volatile("cp.async.commit_group;");
    };

    const int rA   = (lane & 7) + ((lane >> 3) & 1) * 8;
    const int colo = (lane >> 4) * 16;

    load_stage(0, 0);
    const int NIT = SEQ / GBK;
    for (int it = 0; it < NIT; it++) {
        if (it + 1 < NIT) {
            load_stage((it + 1) & 1, (it + 1) * GBK);
            asm volatile("cp.async.wait_group 1;");
        } else {
            asm volatile("cp.async.wait_group 0;");
        }
        __syncthreads();

        const uint32_t st = sbase + (it & 1) * STAGEB;
        unsigned ah[4][4], al[4][4], bh[4][2], bl[4][2];
#pragma unroll
        for (int mi = 0; mi < 4; mi++) {
            uint32_t ad = st + (uint32_t)((wm * 64 + mi * 16 + rA) * SROW) * 2 + colo;
            LDM4(ah[mi], ad);
            LDM4(al[mi], ad + MATB);
        }
#pragma unroll
        for (int nj = 0; nj < 2; nj++) {
            uint32_t bd = st + 2 * MATB + (uint32_t)((wn * 32 + nj * 16 + rA) * SROW) * 2 + colo;
            unsigned r[4];
            LDM4(r, bd);
            bh[2 * nj][0] = r[0]; bh[2 * nj + 1][0] = r[1];
            bh[2 * nj][1] = r[2]; bh[2 * nj + 1][1] = r[3];
            LDM4(r, bd + MATB);
            bl[2 * nj][0] = r[0]; bl[2 * nj + 1][0] = r[1];
            bl[2 * nj][1] = r[2]; bl[2 * nj + 1][1] = r[3];
        }
#pragma unroll
        for (int mi = 0; mi < 4; mi++)
#pragma unroll
            for (int ni = 0; ni < 4; ni++) {
                MMA_BF16(c[mi][ni], ah[mi], bh[ni]);
                MMA_BF16(c[mi][ni], ah[mi], bl[ni]);
                MMA_BF16(c[mi][ni], al[mi], bh[ni]);
            }
        __syncthreads();
    }

#pragma unroll
    for (int mi = 0; mi < 4; mi++) {
        int r0 = bm + wm * 64 + mi * 16 + g;
#pragma unroll
        for (int ni = 0; ni < 4; ni++) {
            int cc = bn + wn * 32 + ni * 8 + 2 * tg;
            float b0 = bias[cc] + 1e-6f;
            float b1 = bias[cc + 1] + 1e-6f;
            g_h[(size_t)r0 * DIM + cc]           = c[mi][ni][0] + b0;
            g_h[(size_t)r0 * DIM + cc + 1]       = c[mi][ni][1] + b1;
            g_h[(size_t)(r0 + 8) * DIM + cc]     = c[mi][ni][2] + b0;
            g_h[(size_t)(r0 + 8) * DIM + cc + 1] = c[mi][ni][3] + b1;
        }
    }
}

// ---------------- kernel 3: circuit, 8 amps/thread, 128 threads (R7 proven) ----------------
__device__ __forceinline__ void rot1(float2 va, float2 vb, float& r, float& i,
                                     float pr, float pi) {
    float nr = va.x * r - va.y * i + vb.x * pr - vb.y * pi;
    float ni = va.x * i + va.y * r + vb.x * pi + vb.y * pr;
    r = nr; i = ni;
}

__global__ __launch_bounds__(128, 8) void circuit_kernel(const float* __restrict__ Wout,
                                                         const float* __restrict__ bout,
                                                         float* __restrict__ out) {
    __shared__ float4 xchg[640];                 // exchange buf (stride-5 float4) / perm stage
    __shared__ float2 sg[NL * NQ * 4];
    __shared__ float  red[4][9];
    __shared__ float  sevn[NQ];
    float2* stage = (float2*)xchg;               // 1024 float2 = 8KB, fits in xchg

    const int t    = threadIdx.x;
    const int lane = t & 31;
    const int b    = blockIdx.x;

    // amp j = 8*t + a : bits 0-2 local, 3-7 lane, 8-9 warp
    const float* hrow = g_h + (size_t)b * DIM + 8 * t;
    float4 hA = *(const float4*)hrow;
    float4 hB = *(const float4*)(hrow + 4);
    float ar[8] = {hA.x, hA.y, hA.z, hA.w, hB.x, hB.y, hB.z, hB.w};
    float ai[8] = {0.f, 0.f, 0.f, 0.f, 0.f, 0.f, 0.f, 0.f};

    for (int i = t; i < NL * NQ * 4; i += 128) sg[i] = g_gates[i];
    __syncthreads();

    for (int l = 0; l < NL; l++) {
        const float2* gl = sg + l * NQ * 4;

        // w=0,1 -> m=9,8 : smem exchange with thread t^64 / t^32
#pragma unroll
        for (int w = 0; w < 2; w++) {
            const float2 u00 = gl[4 * w + 0], u01 = gl[4 * w + 1];
            const float2 u10 = gl[4 * w + 2], u11 = gl[4 * w + 3];
            const int pmask = w ? 32 : 64;
#pragma unroll
            for (int k = 0; k < 4; k++)
                xchg[t * 5 + k] = make_float4(ar[2 * k], ai[2 * k], ar[2 * k + 1], ai[2 * k + 1]);
            __syncthreads();
            const int pth = t ^ pmask;
            float4 o0 = xchg[pth * 5 + 0];
            float4 o1 = xchg[pth * 5 + 1];
            float4 o2 = xchg[pth * 5 + 2];
            float4 o3 = xchg[pth * 5 + 3];
            __syncthreads();
            const bool hib = (t & pmask) != 0;
            const float2 va = hib ? u11 : u00;
            const float2 vb = hib ? u10 : u01;
            rot1(va, vb, ar[0], ai[0], o0.x, o0.y);
            rot1(va, vb, ar[1], ai[1], o0.z, o0.w);
            rot1(va, vb, ar[2], ai[2], o1.x, o1.y);
            rot1(va, vb, ar[3], ai[3], o1.z, o1.w);
            rot1(va, vb, ar[4], ai[4], o2.x, o2.y);
            rot1(va, vb, ar[5], ai[5], o2.z, o2.w);
            rot1(va, vb, ar[6], ai[6], o3.x, o3.y);
            rot1(va, vb, ar[7], ai[7], o3.z, o3.w);
        }

        // w=2..6 -> m=7..3 : shfl over lane bit (6-w)
#pragma unroll
        for (int w = 2; w < 7; w++) {
            const float2 u00 = gl[4 * w + 0], u01 = gl[4 * w + 1];
            const float2 u10 = gl[4 * w + 2], u11 = gl[4 * w + 3];
            const int msk = 1 << (6 - w);
            const bool hib = (lane & msk) != 0;
            const float2 va = hib ? u11 : u00;
            const float2 vb = hib ? u10 : u01;
#pragma unroll
            for (int a = 0; a < 8; a++) {
                float pr = __shfl_xor_sync(0xffffffffu, ar[a], msk);
                float pi = __shfl_xor_sync(0xffffffffu, ai[a], msk);
                rot1(va, vb, ar[a], ai[a], pr, pi);
            }
        }

        // w=7,8,9 -> m=2,1,0 : local pairs
#pragma unroll
        for (int w = 7; w < 10; w++) {
            const float2 u00 = gl[4 * w + 0], u01 = gl[4 * w + 1];
            const float2 u10 = gl[4 * w + 2], u11 = gl[4 * w + 3];
            const int dm = 1 << (9 - w);
#pragma unroll
            for (int a = 0; a < 8; a++) {
                if (!(a & dm)) {
                    float lr = ar[a], li = ai[a];
                    float hr = ar[a + dm], hi2 = ai[a + dm];
                    ar[a]      = u00.x * lr - u00.y * li + u01.x * hr - u01.y * hi2;
                    ai[a]      = u00.x * li + u00.y * lr + u01.x * hi2 + u01.y * hr;
                    ar[a + dm] = u10.x * lr - u10.y * li + u11.x * hr - u11.y * hi2;
                    ai[a + dm] = u10.x * li + u10.y * lr + u11.x * hi2 + u11.y * hr;
                }
            }
        }

        // layer permutation: psi_new[j] = psi[perm[j]]; stage layout [a-plane][t]
#pragma unroll
        for (int a = 0; a < 8; a++) stage[a * 128 + t] = make_float2(ar[a], ai[a]);
        __syncthreads();
        const int* pm = g_perm + l * DIM + 8 * t;
        int4 pa = *(const int4*)pm;
        int4 pb = *(const int4*)(pm + 4);
        int pp[8] = {pa.x, pa.y, pa.z, pa.w, pb.x, pb.y, pb.z, pb.w};
        float2 nv[8];
#pragma unroll
        for (int a = 0; a < 8; a++) {
            int p = pp[a];
            nv[a] = stage[(p & 7) * 128 + (p >> 3)];
        }
        __syncthreads();
#pragma unroll
        for (int a = 0; a < 8; a++) { ar[a] = nv[a].x; ai[a] = nv[a].y; }
    }

    // expvals (unnormalized; divide by total prob at the end)
    float p[8];
#pragma unroll
    for (int a = 0; a < 8; a++) p[a] = ar[a] * ar[a] + ai[a] * ai[a];
    float ps = ((p[0] + p[1]) + (p[2] + p[3])) + ((p[4] + p[5]) + (p[6] + p[7]));

    float v[9];
    v[0] = ps;
#pragma unroll
    for (int i = 0; i < 5; i++)                              // q = 2+i, lane bit 4-i
        v[1 + i] = ((lane >> (4 - i)) & 1) ? -ps : ps;
    v[6] = ((p[0] + p[1]) + (p[2] + p[3])) - ((p[4] + p[5]) + (p[6] + p[7]));  // q7
    v[7] = ((p[0] + p[1]) + (p[4] + p[5])) - ((p[2] + p[3]) + (p[6] + p[7]));  // q8
    v[8] = ((p[0] + p[2]) + (p[4] + p[6])) - ((p[1] + p[3]) + (p[5] + p[7]));  // q9

#pragma unroll
    for (int j = 0; j < 9; j++) {
#pragma unroll
        for (int o = 16; o; o >>= 1) v[j] += __shfl_xor_sync(0xffffffffu, v[j], o);
    }
    if (lane == 0) {
        int wi = t >> 5;
#pragma unroll
        for (int j = 0; j < 9; j++) red[wi][j] = v[j];
    }
    __syncthreads();

    if (t < NQ) {
        const int q = t;
        float pst = ((red[0][0] + red[1][0]) + (red[2][0] + red[3][0]));
        float e;
        if (q >= 2) {
            e = ((red[0][q - 1] + red[1][q - 1]) + (red[2][q - 1] + red[3][q - 1]));
        } else if (q == 0) {   // j bit9 = warp bit1
            e = (red[0][0] + red[1][0]) - (red[2][0] + red[3][0]);
        } else {               // j bit8 = warp bit0
            e = (red[0][0] - red[1][0]) + (red[2][0] - red[3][0]);
        }
        sevn[q] = e / pst;
    }
    __syncthreads();

    if (t < PRED) {
        float o = bout[t];
#pragma unroll
        for (int q = 0; q < NQ; q++) o += sevn[q] * Wout[t * NQ + q];
        out[(size_t)b * PRED + t] = o;
    }
}

// ---------------- launch ----------------
extern "C" void kernel_launch(void* const* d_in, const int* in_sizes, int n_in,
                              void* d_out, int out_size) {
    const float* x     = (const float*)d_in[0];
    const float* W_in  = (const float*)d_in[1];
    const float* b_in  = (const float*)d_in[2];
    const float* qw    = (const float*)d_in[3];
    const float* W_out = (const float*)d_in[4];
    const float* b_out = (const float*)d_in[5];
    float* out = (float*)d_out;

    split_kernel<<<(BATCH * SEQ / 4 + 255) / 256, 256>>>(x, W_in, qw);
    dim3 grid(DIM / GBN, BATCH / GBM);
    gemm_tc<<<grid, 256>>>(b_in);
    circuit_kernel<<<BATCH, 128>>>(W_out, b_out, out);
}